// round 5
// baseline (speedup 1.0000x reference)
#include <cuda_runtime.h>
#include <cuda_fp16.h>
#include <cstdint>

#define BB 4
#define NN 4096
#define EE 2048
#define CC 64
#define ECAP 352   // mean deg_e=205, sd~14
#define NCAP 208   // mean deg_n=102, sd~10
#define EBW 128    // bitmap words per edge (4096 bits)

typedef unsigned long long ull;
typedef unsigned short u16;

// ---- scratch (no cudaMalloc allowed) ----
__device__ __half g_xt[BB * NN * CC];                 // 2 MB (fp16)
__device__ __half g_he[BB * EE * CC];                 // 1 MB (fp16)
__device__ int    g_ecnt[BB * EE];
__device__ int    g_ncnt[BB * NN];
__device__ unsigned g_ebm[(size_t)BB * EE * EBW];     // 4 MB edge bitmaps
__device__ u16    g_elist[(size_t)BB * EE * ECAP];    // 5.8 MB
__device__ u16    g_nlist[(size_t)BB * NN * NCAP];    // 6.8 MB

__device__ __forceinline__ ull fadd2(ull a, ull b) {
    ull d;
    asm("add.rn.f32x2 %0, %1, %2;" : "=l"(d) : "l"(a), "l"(b));
    return d;
}
// accumulate a half2 (as raw u32) into a packed-f32x2 accumulator
__device__ __forceinline__ ull h2acc(ull acc, unsigned h) {
    __half2 hv = *reinterpret_cast<__half2*>(&h);
    float2 f = __half22float2(hv);
    return fadd2(acc, *reinterpret_cast<ull*>(&f));
}

// ---------------- K0: zero edge bitmaps ----------------
__global__ __launch_bounds__(256) void zero_kernel() {
    const int t = blockIdx.x * 256 + threadIdx.x;   // 262144 threads * uint4
    ((uint4*)g_ebm)[t] = make_uint4(0u, 0u, 0u, 0u);
}

// ---------------- K1: xt = x @ theta (warp per row, fp16 out) ----------------
__global__ __launch_bounds__(256)
void xt_kernel(const float* __restrict__ x, const float* __restrict__ theta) {
    __shared__ float th[CC * 66];
    const int tid = threadIdx.x;
    for (int i = tid; i < CC * CC; i += 256) {
        int k = i >> 6, c = i & 63;
        th[k * 66 + c] = theta[i];
    }
    __syncthreads();

    const int lane = tid & 31;
    const int row = blockIdx.x * 8 + (tid >> 5);
    const float2 xv = ((const float2*)(x + (size_t)row * CC))[lane];
    float a0 = 0.f, a1 = 0.f;
#pragma unroll
    for (int k = 0; k < CC; k++) {
        const float xs = (k & 1) ? __shfl_sync(0xffffffffu, xv.y, k >> 1)
                                 : __shfl_sync(0xffffffffu, xv.x, k >> 1);
        const float2 t = *(const float2*)&th[k * 66 + lane * 2];
        a0 = fmaf(xs, t.x, a0);
        a1 = fmaf(xs, t.y, a1);
    }
    ((__half2*)(g_xt + (size_t)row * CC))[lane] = __float22half2_rn(make_float2(a0, a1));
}

// ---------------- K2: build (warp per node row; one coalesced H pass) ----------------
__global__ __launch_bounds__(256)
void build_kernel(const float* __restrict__ H) {
    const int lane = threadIdx.x & 31;
    const int gw = blockIdx.x * 8 + (threadIdx.x >> 5);   // (b,n)
    const int n = gw & (NN - 1);
    const int b = gw >> 12;

    const float4* __restrict__ Hrow = (const float4*)(H + (size_t)gw * EE);
    unsigned* __restrict__ ebm = g_ebm + (size_t)b * EE * EBW + (n >> 5);
    u16* __restrict__ nl = g_nlist + (size_t)gw * NCAP;
    const unsigned bitv = 1u << (n & 31);
    const unsigned lt = (1u << lane) - 1u;

    int wcount = 0;
    float4 h = Hrow[lane];
#pragma unroll
    for (int chunk = 0; chunk < 16; chunk++) {
        float4 hn;
        if (chunk < 15) hn = Hrow[(chunk + 1) * 32 + lane];

        const int e0 = chunk * 128 + lane * 4;
        const int c0 = h.x != 0.f, c1 = h.y != 0.f, c2 = h.z != 0.f, c3 = h.w != 0.f;

        if (c0) atomicOr(&ebm[(size_t)(e0 + 0) * EBW], bitv);
        if (c1) atomicOr(&ebm[(size_t)(e0 + 1) * EBW], bitv);
        if (c2) atomicOr(&ebm[(size_t)(e0 + 2) * EBW], bitv);
        if (c3) atomicOr(&ebm[(size_t)(e0 + 3) * EBW], bitv);

        const unsigned b0 = __ballot_sync(0xffffffffu, c0);
        const unsigned b1 = __ballot_sync(0xffffffffu, c1);
        const unsigned b2 = __ballot_sync(0xffffffffu, c2);
        const unsigned b3 = __ballot_sync(0xffffffffu, c3);
        int base = wcount;
        if (c0) { int p = base + __popc(b0 & lt); if (p < NCAP) nl[p] = (u16)e0; }
        base += __popc(b0);
        if (c1) { int p = base + __popc(b1 & lt); if (p < NCAP) nl[p] = (u16)(e0 + 1); }
        base += __popc(b1);
        if (c2) { int p = base + __popc(b2 & lt); if (p < NCAP) nl[p] = (u16)(e0 + 2); }
        base += __popc(b2);
        if (c3) { int p = base + __popc(b3 & lt); if (p < NCAP) nl[p] = (u16)(e0 + 3); }
        base += __popc(b3);
        wcount = base;

        h = hn;
    }
    if (lane == 0) g_ncnt[gw] = wcount;
}

// ---------------- K3: decode edge bitmaps -> edge lists ----------------
__global__ __launch_bounds__(256)
void decode_kernel() {
    const int lane = threadIdx.x & 31;
    const int gw = blockIdx.x * 8 + (threadIdx.x >> 5);   // (b,e)

    const uint4 wv = ((const uint4*)(g_ebm + (size_t)gw * EBW))[lane];
    const int cnt = __popc(wv.x) + __popc(wv.y) + __popc(wv.z) + __popc(wv.w);

    int pre = cnt;
#pragma unroll
    for (int d = 1; d < 32; d <<= 1) {
        int v = __shfl_up_sync(0xffffffffu, pre, d);
        if (lane >= d) pre += v;
    }
    const int total = __shfl_sync(0xffffffffu, pre, 31);
    int w = pre - cnt;

    u16* __restrict__ el = g_elist + (size_t)gw * ECAP;
    const int nb = lane * 128;
    unsigned words[4] = {wv.x, wv.y, wv.z, wv.w};
#pragma unroll
    for (int k = 0; k < 4; k++) {
        unsigned bits = words[k];
        while (bits) {
            const int t = __ffs(bits) - 1;
            bits &= bits - 1;
            if (w < ECAP) el[w] = (u16)(nb + k * 32 + t);
            w++;
        }
    }
    if (lane == 0) g_ecnt[gw] = total;
}

// ---------------- K4/K5: sparse mean-aggregation over fp16 rows ----------------
// 8 lanes per gathered row (128B), 4 rows concurrently per warp; fp32 accum.
// OUTHALF: dst is __half rows (he); else float rows (final out).
template <bool HASBIAS, bool OUTHALF>
__global__ __launch_bounds__(256)
void agg_kernel(const u16* __restrict__ list, const int* __restrict__ cnts,
                const __half* __restrict__ src, void* __restrict__ dstv,
                const float* __restrict__ bias, int M, int SRCROWS, int CAP) {
    const int gt = blockIdx.x * 256 + threadIdx.x;
    const int lane = gt & 31;
    const int g = lane >> 3;           // row group 0..3
    const int c = lane & 7;            // 16B chunk within row (8 cols)
    const int gw = gt >> 5;            // (b,m)
    const int b = gw / M;
    const int deg = cnts[gw];
    const u16* __restrict__ L = list + (size_t)gw * CAP;
    const uint4* __restrict__ S = (const uint4*)(src + (size_t)b * SRCROWS * CC);

    ull a0 = 0ull, a1 = 0ull, a2 = 0ull, a3 = 0ull;   // 8 fp32 cols: c*8..c*8+7
    int i = 0;
    for (; i + 32 <= deg; i += 32) {
        const int idx = (int)L[i + lane];
#pragma unroll
        for (int j = 0; j < 8; j++) {
            const int n = __shfl_sync(0xffffffffu, idx, j * 4 + g);
            const uint4 v = S[(size_t)n * 8 + c];
            a0 = h2acc(a0, v.x);
            a1 = h2acc(a1, v.y);
            a2 = h2acc(a2, v.z);
            a3 = h2acc(a3, v.w);
        }
    }
    if (i < deg) {
        const int r = deg - i;
        const int idx = (i + lane < deg) ? (int)L[i + lane] : 0;
        for (int j = 0; j < r; j++) {
            if ((j & 3) == g) {
                const int n = __shfl_sync(0xffffffffu, idx, j);
                const uint4 v = S[(size_t)n * 8 + c];
                a0 = h2acc(a0, v.x);
                a1 = h2acc(a1, v.y);
                a2 = h2acc(a2, v.z);
                a3 = h2acc(a3, v.w);
            } else {
                __shfl_sync(0xffffffffu, idx, j);
            }
        }
    }

    // unpack 4 packed accumulators -> 8 floats, reduce across the 4 row groups
    float v[8];
    *(float2*)&v[0] = *(float2*)&a0;
    *(float2*)&v[2] = *(float2*)&a1;
    *(float2*)&v[4] = *(float2*)&a2;
    *(float2*)&v[6] = *(float2*)&a3;
#pragma unroll
    for (int k = 0; k < 8; k++) v[k] += __shfl_xor_sync(0xffffffffu, v[k], 8);
#pragma unroll
    for (int k = 0; k < 8; k++) v[k] += __shfl_xor_sync(0xffffffffu, v[k], 16);

    const float inv = 1.0f / (float)deg;
#pragma unroll
    for (int k = 0; k < 8; k++) v[k] *= inv;
    if (HASBIAS) {
        const float4 bv0 = *(const float4*)&bias[c * 8];
        const float4 bv1 = *(const float4*)&bias[c * 8 + 4];
        v[0] += bv0.x; v[1] += bv0.y; v[2] += bv0.z; v[3] += bv0.w;
        v[4] += bv1.x; v[5] += bv1.y; v[6] += bv1.z; v[7] += bv1.w;
    }

    if (g == 0) {
        if (OUTHALF) {
            __half* drow = (__half*)dstv + (size_t)gw * CC;
            uint4 o;
            __half2 h0 = __float22half2_rn(make_float2(v[0], v[1]));
            __half2 h1 = __float22half2_rn(make_float2(v[2], v[3]));
            __half2 h2 = __float22half2_rn(make_float2(v[4], v[5]));
            __half2 h3 = __float22half2_rn(make_float2(v[6], v[7]));
            o.x = *(unsigned*)&h0; o.y = *(unsigned*)&h1;
            o.z = *(unsigned*)&h2; o.w = *(unsigned*)&h3;
            ((uint4*)drow)[c] = o;
        } else {
            float* drow = (float*)dstv + (size_t)gw * CC;
            *(float4*)&drow[c * 8]     = make_float4(v[0], v[1], v[2], v[3]);
            *(float4*)&drow[c * 8 + 4] = make_float4(v[4], v[5], v[6], v[7]);
        }
    }
}

// ---------------- launch ----------------
extern "C" void kernel_launch(void* const* d_in, const int* in_sizes, int n_in,
                              void* d_out, int out_size) {
    const float* x = (const float*)d_in[0];
    const float* H = (const float*)d_in[1];
    const float* theta = (const float*)d_in[2];
    const float* bias = (const float*)d_in[3];
    float* out = (float*)d_out;

    __half *xt, *he;
    int *ecnt, *ncnt;
    u16 *elist, *nlist;
    cudaGetSymbolAddress((void**)&xt, g_xt);
    cudaGetSymbolAddress((void**)&he, g_he);
    cudaGetSymbolAddress((void**)&ecnt, g_ecnt);
    cudaGetSymbolAddress((void**)&ncnt, g_ncnt);
    cudaGetSymbolAddress((void**)&elist, g_elist);
    cudaGetSymbolAddress((void**)&nlist, g_nlist);

    // K0: zero 4MB edge bitmaps
    zero_kernel<<<1024, 256>>>();
    // K1: node transform -> fp16 xt
    xt_kernel<<<(BB * NN) / 8, 256>>>(x, theta);
    // K2: one coalesced H pass -> node lists (u16) + edge bitmaps
    build_kernel<<<(BB * NN) / 8, 256>>>(H);
    // K3: bitmaps -> edge lists (u16) + counts
    decode_kernel<<<(BB * EE) / 8, 256>>>();
    // K4: he = mean_{n in e} xt[n]   (fp16 out)
    agg_kernel<false, true><<<(BB * EE) / 8, 256>>>(elist, ecnt, xt, he, nullptr, EE, NN, ECAP);
    // K5: out = mean_{e in n} he[e] + bias   (fp32 out)
    agg_kernel<true, false><<<(BB * NN) / 8, 256>>>(nlist, ncnt, he, out, bias, NN, EE, NCAP);
}

// round 6
// speedup vs baseline: 1.4265x; 1.4265x over previous
#include <cuda_runtime.h>
#include <cstdint>

#define BB 4
#define NN 4096
#define EE 2048
#define CC 64
#define ECAP 352   // deg_e mean 205, sd~14
#define NCAP 224   // deg_n mean 102, sd~10
#define EBW 128    // words per edge bitmap (4096 node bits)
#define NBW 64     // words per node bitmap (2048 edge bits)

typedef unsigned long long ull;
typedef unsigned short u16;

// ---- scratch (no cudaMalloc allowed) ----
__device__ float    g_xt[BB * NN * CC];               // 4 MB
__device__ float    g_he[BB * EE * CC];               // 2 MB
__device__ unsigned g_ebm[(size_t)BB * EE * EBW];     // 4 MB edge bitmaps (atomicOr)
__device__ unsigned g_nbm[(size_t)BB * NN * NBW];     // 4 MB node bitmaps (ballot words)

__device__ __forceinline__ ull fadd2(ull a, ull b) {
    ull d;
    asm("add.rn.f32x2 %0, %1, %2;" : "=l"(d) : "l"(a), "l"(b));
    return d;
}

// ---------------- K0: zero edge bitmaps (node bitmaps fully overwritten) ------------
__global__ __launch_bounds__(256) void zero_kernel() {
    const int t = blockIdx.x * 256 + threadIdx.x;   // 262144 * uint4 = 4 MB
    ((uint4*)g_ebm)[t] = make_uint4(0u, 0u, 0u, 0u);
}

// ---------------- K1: xt = x @ theta (warp per row) ----------------
__global__ __launch_bounds__(256)
void xt_kernel(const float* __restrict__ x, const float* __restrict__ theta,
               float* __restrict__ xt) {
    __shared__ float th[CC * 66];
    const int tid = threadIdx.x;
    for (int i = tid; i < CC * CC; i += 256) {
        int k = i >> 6, c = i & 63;
        th[k * 66 + c] = theta[i];
    }
    __syncthreads();

    const int lane = tid & 31;
    const int row = blockIdx.x * 8 + (tid >> 5);
    const float2 xv = ((const float2*)(x + (size_t)row * CC))[lane];
    float a0 = 0.f, a1 = 0.f;
#pragma unroll
    for (int k = 0; k < CC; k++) {
        const float xs = (k & 1) ? __shfl_sync(0xffffffffu, xv.y, k >> 1)
                                 : __shfl_sync(0xffffffffu, xv.x, k >> 1);
        const float2 t = *(const float2*)&th[k * 66 + lane * 2];
        a0 = fmaf(xs, t.x, a0);
        a1 = fmaf(xs, t.y, a1);
    }
    ((float2*)(xt + (size_t)row * CC))[lane] = make_float2(a0, a1);
}

// ---------------- K2: build — one coalesced H pass -> both bitmaps ----------------
// Node bitmap is stored in "ballot layout": word w = chunk*4+q holds, at bit l,
// the H value for edge e = chunk*128 + 4*l + q. Decoded by agg_n accordingly.
__global__ __launch_bounds__(256)
void build_kernel(const float* __restrict__ H) {
    const int lane = threadIdx.x & 31;
    const int gw = blockIdx.x * 8 + (threadIdx.x >> 5);   // (b,n)
    const int n = gw & (NN - 1);
    const int b = gw >> 12;

    const float4* __restrict__ Hrow = (const float4*)(H + (size_t)gw * EE);
    unsigned* __restrict__ ebm = g_ebm + (size_t)b * EE * EBW + (n >> 5);
    const unsigned bitv = 1u << (n & 31);

    unsigned nw0 = 0, nw1 = 0;   // this lane's two node-bitmap words
    float4 h = Hrow[lane];
#pragma unroll
    for (int chunk = 0; chunk < 16; chunk++) {
        float4 hn;
        if (chunk < 15) hn = Hrow[(chunk + 1) * 32 + lane];

        const int e0 = chunk * 128 + lane * 4;
        const int c0 = h.x != 0.f, c1 = h.y != 0.f, c2 = h.z != 0.f, c3 = h.w != 0.f;

        // edge bitmaps: fire-and-forget RED.OR
        if (c0) atomicOr(&ebm[(size_t)(e0 + 0) * EBW], bitv);
        if (c1) atomicOr(&ebm[(size_t)(e0 + 1) * EBW], bitv);
        if (c2) atomicOr(&ebm[(size_t)(e0 + 2) * EBW], bitv);
        if (c3) atomicOr(&ebm[(size_t)(e0 + 3) * EBW], bitv);

        // node bitmap: the ballots ARE the words (permuted layout)
        const unsigned b0 = __ballot_sync(0xffffffffu, c0);
        const unsigned b1 = __ballot_sync(0xffffffffu, c1);
        const unsigned b2 = __ballot_sync(0xffffffffu, c2);
        const unsigned b3 = __ballot_sync(0xffffffffu, c3);
        if (lane == 2 * chunk)          { nw0 = b0; nw1 = b1; }
        else if (lane == 2 * chunk + 1) { nw0 = b2; nw1 = b3; }

        h = hn;
    }
    ((uint2*)(g_nbm + (size_t)gw * NBW))[lane] = make_uint2(nw0, nw1);
}

// ---------------- K3/K4: aggregation with fused bitmap decode ----------------
// Warp per output row. Stage: expand this row's bitmap to a smem u16 index list.
// Gather: half-warp float4 (16 lanes/row, 4 rows in flight), fp32 packed accum.
// NATURAL: bit t of word w -> idx w*32+t ; else ballot layout (see build_kernel).
template <int WPL, int CAP, bool HASBIAS, bool NATURAL>
__global__ __launch_bounds__(256)
void agg_kernel(const unsigned* __restrict__ bm, const float* __restrict__ src,
                float* __restrict__ dst, const float* __restrict__ bias,
                int M, int SRCROWS) {
    __shared__ u16 sidx[8][CAP];

    const int tid = threadIdx.x;
    const int lane = tid & 31;
    const int wid = tid >> 5;
    const int gw = blockIdx.x * 8 + wid;   // (b,m)
    const int b = gw / M;

    // ---- decode bitmap -> smem index list ----
    unsigned w[WPL];
    const unsigned* __restrict__ W = bm + (size_t)gw * (WPL * 32);
    if (WPL == 4) {
        const uint4 v = ((const uint4*)W)[lane];
        w[0] = v.x; w[1] = v.y; w[2] = v.z; w[3] = v.w;
    } else {
        const uint2 v = ((const uint2*)W)[lane];
        w[0] = v.x; w[1] = v.y;
    }
    int cnt = 0;
#pragma unroll
    for (int k = 0; k < WPL; k++) cnt += __popc(w[k]);

    int pre = cnt;
#pragma unroll
    for (int d = 1; d < 32; d <<= 1) {
        int v = __shfl_up_sync(0xffffffffu, pre, d);
        if (lane >= d) pre += v;
    }
    const int deg = __shfl_sync(0xffffffffu, pre, 31);
    int off = pre - cnt;

    u16* __restrict__ s = sidx[wid];
#pragma unroll
    for (int k = 0; k < WPL; k++) {
        const int wi = lane * WPL + k;
        unsigned bits = w[k];
        while (bits) {
            const int t = __ffs(bits) - 1;
            bits &= bits - 1;
            const int idx = NATURAL ? (wi * 32 + t)
                                    : (((wi >> 2) << 7) + (wi & 3) + (t << 2));
            if (off < CAP) s[off] = (u16)idx;
            off++;
        }
    }
    __syncwarp();

    // ---- gather ----
    const int half = lane >> 4;        // 0 / 1
    const int hl = lane & 15;          // float4 column group
    const float4* __restrict__ S = (const float4*)src + (size_t)b * SRCROWS * (CC / 4);

    ull accA = 0ull, accB = 0ull;
    int i = 0;
    for (; i + 4 <= deg; i += 4) {
        const int n0 = (int)s[i + half];
        const int n1 = (int)s[i + 2 + half];
        const float4 v0 = S[(size_t)n0 * (CC / 4) + hl];
        const float4 v1 = S[(size_t)n1 * (CC / 4) + hl];
        accA = fadd2(accA, *(const ull*)&v0.x);
        accB = fadd2(accB, *(const ull*)&v0.z);
        accA = fadd2(accA, *(const ull*)&v1.x);
        accB = fadd2(accB, *(const ull*)&v1.z);
    }
    if (i + 2 <= deg) {
        const int n = (int)s[i + half];
        const float4 v = S[(size_t)n * (CC / 4) + hl];
        accA = fadd2(accA, *(const ull*)&v.x);
        accB = fadd2(accB, *(const ull*)&v.z);
        i += 2;
    }
    if (i < deg && half == 0) {
        const int n = (int)s[i];
        const float4 v = S[(size_t)n * (CC / 4) + hl];
        accA = fadd2(accA, *(const ull*)&v.x);
        accB = fadd2(accB, *(const ull*)&v.z);
    }

    // combine halves
    float4 a;
    a.x = ((const float2*)&accA)->x;
    a.y = ((const float2*)&accA)->y;
    a.z = ((const float2*)&accB)->x;
    a.w = ((const float2*)&accB)->y;
    a.x += __shfl_xor_sync(0xffffffffu, a.x, 16);
    a.y += __shfl_xor_sync(0xffffffffu, a.y, 16);
    a.z += __shfl_xor_sync(0xffffffffu, a.z, 16);
    a.w += __shfl_xor_sync(0xffffffffu, a.w, 16);

    const float inv = 1.0f / (float)deg;   // degrees guaranteed > 0
    a.x *= inv; a.y *= inv; a.z *= inv; a.w *= inv;
    if (HASBIAS) {
        const float4 bv = ((const float4*)bias)[hl];
        a.x += bv.x; a.y += bv.y; a.z += bv.z; a.w += bv.w;
    }
    if (half == 0)
        ((float4*)(dst + (size_t)gw * CC))[hl] = a;
}

// ---------------- launch ----------------
extern "C" void kernel_launch(void* const* d_in, const int* in_sizes, int n_in,
                              void* d_out, int out_size) {
    const float* x = (const float*)d_in[0];
    const float* H = (const float*)d_in[1];
    const float* theta = (const float*)d_in[2];
    const float* bias = (const float*)d_in[3];
    float* out = (float*)d_out;

    float *xt, *he;
    unsigned *ebm, *nbm;
    cudaGetSymbolAddress((void**)&xt, g_xt);
    cudaGetSymbolAddress((void**)&he, g_he);
    cudaGetSymbolAddress((void**)&ebm, g_ebm);
    cudaGetSymbolAddress((void**)&nbm, g_nbm);

    // K0: zero edge bitmaps (4 MB)
    zero_kernel<<<1024, 256>>>();
    // K1: node transform
    xt_kernel<<<(BB * NN) / 8, 256>>>(x, theta, xt);
    // K2: one coalesced H pass -> node bitmaps (deterministic) + edge bitmaps (RED.OR)
    build_kernel<<<(BB * NN) / 8, 256>>>(H);
    // K3: he = mean_{n in e} xt[n]   (decode ebm inline; natural bit layout)
    agg_kernel<4, ECAP, false, true>
        <<<(BB * EE) / 8, 256>>>(ebm, xt, he, nullptr, EE, NN);
    // K4: out = mean_{e in n} he[e] + bias   (decode nbm inline; ballot layout)
    agg_kernel<2, NCAP, true, false>
        <<<(BB * NN) / 8, 256>>>(nbm, he, out, bias, NN, EE);
}

// round 7
// speedup vs baseline: 1.4334x; 1.0048x over previous
#include <cuda_runtime.h>
#include <cstdint>

#define BB 4
#define NN 4096
#define EE 2048
#define CC 64
#define ECAP 352   // deg_e mean 205, sd~14
#define NCAP 224   // deg_n mean 102, sd~10
#define EBW 128    // words per edge bitmap (4096 node bits)
#define NBW 64     // words per node bitmap (2048 edge bits)

typedef unsigned long long ull;
typedef unsigned short u16;

// ---- scratch (no cudaMalloc allowed) ----
__device__ float    g_xt[BB * NN * CC];               // 4 MB
__device__ float    g_he[BB * EE * CC];               // 2 MB
__device__ unsigned g_ebm[(size_t)BB * EE * EBW];     // 4 MB edge bitmaps (atomicOr)
__device__ unsigned g_nbm[(size_t)BB * NN * NBW];     // 4 MB node bitmaps (ballot words)

__device__ __forceinline__ ull fadd2(ull a, ull b) {
    ull d;
    asm("add.rn.f32x2 %0, %1, %2;" : "=l"(d) : "l"(a), "l"(b));
    return d;
}

// ---------------- K0: zero edge bitmaps ----------------
__global__ __launch_bounds__(256) void zero_kernel() {
    const int t = blockIdx.x * 256 + threadIdx.x;   // 262144 * uint4 = 4 MB
    ((uint4*)g_ebm)[t] = make_uint4(0u, 0u, 0u, 0u);
}

// ---------------- K1: xt = x @ theta (warp per row) ----------------
__global__ __launch_bounds__(256)
void xt_kernel(const float* __restrict__ x, const float* __restrict__ theta,
               float* __restrict__ xt) {
    __shared__ float th[CC * 66];
    const int tid = threadIdx.x;
    for (int i = tid; i < CC * CC; i += 256) {
        int k = i >> 6, c = i & 63;
        th[k * 66 + c] = theta[i];
    }
    __syncthreads();

    const int lane = tid & 31;
    const int row = blockIdx.x * 8 + (tid >> 5);
    const float2 xv = ((const float2*)(x + (size_t)row * CC))[lane];
    float a0 = 0.f, a1 = 0.f;
#pragma unroll
    for (int k = 0; k < CC; k++) {
        const float xs = (k & 1) ? __shfl_sync(0xffffffffu, xv.y, k >> 1)
                                 : __shfl_sync(0xffffffffu, xv.x, k >> 1);
        const float2 t = *(const float2*)&th[k * 66 + lane * 2];
        a0 = fmaf(xs, t.x, a0);
        a1 = fmaf(xs, t.y, a1);
    }
    ((float2*)(xt + (size_t)row * CC))[lane] = make_float2(a0, a1);
}

// ---------------- K2: build — 2 warps per node row -> both bitmaps ----------------
// Node bitmap "ballot layout": word w = chunk*4+q holds, at bit l, H value for
// edge e = chunk*128 + 4*l + q.
__global__ __launch_bounds__(256)
void build_kernel(const float* __restrict__ H) {
    const int tid = threadIdx.x;
    const int lane = tid & 31;
    const int w2 = (tid >> 5) & 1;                      // which half of the row
    const int gw = blockIdx.x * 4 + (tid >> 6);         // (b,n)
    const int n = gw & (NN - 1);
    const int b = gw >> 12;

    const float4* __restrict__ Hrow = (const float4*)(H + (size_t)gw * EE);
    unsigned* __restrict__ ebm = g_ebm + (size_t)b * EE * EBW + (n >> 5);
    const unsigned bitv = 1u << (n & 31);

    const int cbase = w2 * 8;                           // chunks [cbase, cbase+8)
    unsigned nw0 = 0, nw1 = 0;
    float4 h = Hrow[cbase * 32 + lane];
#pragma unroll
    for (int lc = 0; lc < 8; lc++) {
        float4 hn;
        if (lc < 7) hn = Hrow[(cbase + lc + 1) * 32 + lane];

        const int e0 = (cbase + lc) * 128 + lane * 4;
        const int c0 = h.x != 0.f, c1 = h.y != 0.f, c2 = h.z != 0.f, c3 = h.w != 0.f;

        if (c0) atomicOr(&ebm[(size_t)(e0 + 0) * EBW], bitv);
        if (c1) atomicOr(&ebm[(size_t)(e0 + 1) * EBW], bitv);
        if (c2) atomicOr(&ebm[(size_t)(e0 + 2) * EBW], bitv);
        if (c3) atomicOr(&ebm[(size_t)(e0 + 3) * EBW], bitv);

        const unsigned b0 = __ballot_sync(0xffffffffu, c0);
        const unsigned b1 = __ballot_sync(0xffffffffu, c1);
        const unsigned b2 = __ballot_sync(0xffffffffu, c2);
        const unsigned b3 = __ballot_sync(0xffffffffu, c3);
        if (lane == 2 * lc)          { nw0 = b0; nw1 = b1; }
        else if (lane == 2 * lc + 1) { nw0 = b2; nw1 = b3; }

        h = hn;
    }
    if (lane < 16)
        ((uint2*)(g_nbm + (size_t)gw * NBW + w2 * 32))[lane] = make_uint2(nw0, nw1);
}

// ---------------- K3/K4: aggregation with fused bitmap decode ----------------
// Warp per output row; decode bitmap -> smem u16 list; gather half-warp float4
// with 8 rows in flight; packed fp32 accumulation.
template <int WPL, int CAP, bool HASBIAS, bool NATURAL, int M, int SRCROWS>
__global__ __launch_bounds__(256)
void agg_kernel(const unsigned* __restrict__ bm, const float* __restrict__ src,
                float* __restrict__ dst, const float* __restrict__ bias) {
    __shared__ u16 sidx[8][CAP];

    const int tid = threadIdx.x;
    const int lane = tid & 31;
    const int wid = tid >> 5;
    const int gw = blockIdx.x * 8 + wid;   // (b,m)
    const int b = gw / M;

    // ---- decode bitmap -> smem index list ----
    unsigned w[WPL];
    const unsigned* __restrict__ W = bm + (size_t)gw * (WPL * 32);
    if (WPL == 4) {
        const uint4 v = ((const uint4*)W)[lane];
        w[0] = v.x; w[1] = v.y; w[2] = v.z; w[3] = v.w;
    } else {
        const uint2 v = ((const uint2*)W)[lane];
        w[0] = v.x; w[1] = v.y;
    }
    int cnt = 0;
#pragma unroll
    for (int k = 0; k < WPL; k++) cnt += __popc(w[k]);

    int pre = cnt;
#pragma unroll
    for (int d = 1; d < 32; d <<= 1) {
        int v = __shfl_up_sync(0xffffffffu, pre, d);
        if (lane >= d) pre += v;
    }
    const int deg = __shfl_sync(0xffffffffu, pre, 31);
    int off = pre - cnt;

    u16* __restrict__ s = sidx[wid];
#pragma unroll
    for (int k = 0; k < WPL; k++) {
        const int wi = lane * WPL + k;
        unsigned bits = w[k];
        while (bits) {
            const int t = __ffs(bits) - 1;
            bits &= bits - 1;
            const int idx = NATURAL ? (wi * 32 + t)
                                    : (((wi >> 2) << 7) + (wi & 3) + (t << 2));
            if (off < CAP) s[off] = (u16)idx;
            off++;
        }
    }
    __syncwarp();

    // ---- gather: 8 rows per iteration (4 per half-warp) ----
    const int half = lane >> 4;
    const int hl = lane & 15;
    const float4* __restrict__ S =
        (const float4*)src + (size_t)b * (SRCROWS * (CC / 4));

    ull accA = 0ull, accB = 0ull;
    int i = 0;
    for (; i + 8 <= deg; i += 8) {
        const int n0 = (int)s[i + half];
        const int n1 = (int)s[i + 2 + half];
        const int n2 = (int)s[i + 4 + half];
        const int n3 = (int)s[i + 6 + half];
        const float4 v0 = S[n0 * (CC / 4) + hl];
        const float4 v1 = S[n1 * (CC / 4) + hl];
        const float4 v2 = S[n2 * (CC / 4) + hl];
        const float4 v3 = S[n3 * (CC / 4) + hl];
        accA = fadd2(accA, *(const ull*)&v0.x);
        accB = fadd2(accB, *(const ull*)&v0.z);
        accA = fadd2(accA, *(const ull*)&v1.x);
        accB = fadd2(accB, *(const ull*)&v1.z);
        accA = fadd2(accA, *(const ull*)&v2.x);
        accB = fadd2(accB, *(const ull*)&v2.z);
        accA = fadd2(accA, *(const ull*)&v3.x);
        accB = fadd2(accB, *(const ull*)&v3.z);
    }
    for (; i + 2 <= deg; i += 2) {
        const int n = (int)s[i + half];
        const float4 v = S[n * (CC / 4) + hl];
        accA = fadd2(accA, *(const ull*)&v.x);
        accB = fadd2(accB, *(const ull*)&v.z);
    }
    if (i < deg && half == 0) {
        const int n = (int)s[i];
        const float4 v = S[n * (CC / 4) + hl];
        accA = fadd2(accA, *(const ull*)&v.x);
        accB = fadd2(accB, *(const ull*)&v.z);
    }

    // combine halves
    float4 a;
    a.x = ((const float2*)&accA)->x;
    a.y = ((const float2*)&accA)->y;
    a.z = ((const float2*)&accB)->x;
    a.w = ((const float2*)&accB)->y;
    a.x += __shfl_xor_sync(0xffffffffu, a.x, 16);
    a.y += __shfl_xor_sync(0xffffffffu, a.y, 16);
    a.z += __shfl_xor_sync(0xffffffffu, a.z, 16);
    a.w += __shfl_xor_sync(0xffffffffu, a.w, 16);

    const float inv = 1.0f / (float)deg;   // degrees guaranteed > 0
    a.x *= inv; a.y *= inv; a.z *= inv; a.w *= inv;
    if (HASBIAS) {
        const float4 bv = ((const float4*)bias)[hl];
        a.x += bv.x; a.y += bv.y; a.z += bv.z; a.w += bv.w;
    }
    if (half == 0)
        ((float4*)(dst + (size_t)gw * CC))[hl] = a;
}

// ---------------- launch ----------------
extern "C" void kernel_launch(void* const* d_in, const int* in_sizes, int n_in,
                              void* d_out, int out_size) {
    const float* x = (const float*)d_in[0];
    const float* H = (const float*)d_in[1];
    const float* theta = (const float*)d_in[2];
    const float* bias = (const float*)d_in[3];
    float* out = (float*)d_out;

    float *xt, *he;
    unsigned *ebm, *nbm;
    cudaGetSymbolAddress((void**)&xt, g_xt);
    cudaGetSymbolAddress((void**)&he, g_he);
    cudaGetSymbolAddress((void**)&ebm, g_ebm);
    cudaGetSymbolAddress((void**)&nbm, g_nbm);

    // K0: zero edge bitmaps (4 MB)
    zero_kernel<<<1024, 256>>>();
    // K1: node transform
    xt_kernel<<<(BB * NN) / 8, 256>>>(x, theta, xt);
    // K2: 2 warps per node row -> node bitmaps + edge bitmaps
    build_kernel<<<(BB * NN) / 4, 256>>>(H);
    // K3: he = mean_{n in e} xt[n]
    agg_kernel<4, ECAP, false, true, EE, NN>
        <<<(BB * EE) / 8, 256>>>(ebm, xt, he, nullptr);
    // K4: out = mean_{e in n} he[e] + bias
    agg_kernel<2, NCAP, true, false, NN, EE>
        <<<(BB * NN) / 8, 256>>>(nbm, he, out, bias);
}

// round 8
// speedup vs baseline: 1.6624x; 1.1598x over previous
#include <cuda_runtime.h>
#include <cuda_fp16.h>
#include <cstdint>

#define BB 4
#define NN 4096
#define EE 2048
#define CC 64
#define ECAP 352   // deg_e mean 205, sd~14
#define NCAP 224   // deg_n mean 102, sd~10
#define EBW 128    // words per edge bitmap (4096 node bits)
#define NBW 64     // words per node bitmap (2048 edge bits)

typedef unsigned long long ull;
typedef unsigned short u16;

// ---- scratch (no cudaMalloc allowed) ----
__device__ __half   g_xt[BB * NN * CC];               // 2 MB (fp16)
__device__ __half   g_he[BB * EE * CC];               // 1 MB (fp16)
__device__ unsigned g_ebm[(size_t)BB * EE * EBW];     // 4 MB edge bitmaps (atomicOr)
__device__ unsigned g_nbm[(size_t)BB * NN * NBW];     // 4 MB node bitmaps (ballot words)

__device__ __forceinline__ ull fadd2(ull a, ull b) {
    ull d;
    asm("add.rn.f32x2 %0, %1, %2;" : "=l"(d) : "l"(a), "l"(b));
    return d;
}
__device__ __forceinline__ ull f2ull(float2 f) { return *reinterpret_cast<ull*>(&f); }

// ---------------- K0: zero edge bitmaps ----------------
__global__ __launch_bounds__(256) void zero_kernel() {
    const int t = blockIdx.x * 256 + threadIdx.x;   // 262144 * uint4 = 4 MB
    ((uint4*)g_ebm)[t] = make_uint4(0u, 0u, 0u, 0u);
}

// ---------------- K1: xt = x @ theta (warp per row, fp16 out) ----------------
__global__ __launch_bounds__(256)
void xt_kernel(const float* __restrict__ x, const float* __restrict__ theta) {
    __shared__ float th[CC * 66];
    const int tid = threadIdx.x;
    for (int i = tid; i < CC * CC; i += 256) {
        int k = i >> 6, c = i & 63;
        th[k * 66 + c] = theta[i];
    }
    __syncthreads();

    const int lane = tid & 31;
    const int row = blockIdx.x * 8 + (tid >> 5);
    const float2 xv = ((const float2*)(x + (size_t)row * CC))[lane];
    float a0 = 0.f, a1 = 0.f;
#pragma unroll
    for (int k = 0; k < CC; k++) {
        const float xs = (k & 1) ? __shfl_sync(0xffffffffu, xv.y, k >> 1)
                                 : __shfl_sync(0xffffffffu, xv.x, k >> 1);
        const float2 t = *(const float2*)&th[k * 66 + lane * 2];
        a0 = fmaf(xs, t.x, a0);
        a1 = fmaf(xs, t.y, a1);
    }
    ((__half2*)(g_xt + (size_t)row * CC))[lane] = __float22half2_rn(make_float2(a0, a1));
}

// ---------------- K2: build — 2 warps per row, 8 loads prefetched upfront ----------
// Node bitmap "ballot layout": word w = chunk*4+q holds, at bit l, H value for
// edge e = chunk*128 + 4*l + q.
__global__ __launch_bounds__(256)
void build_kernel(const float* __restrict__ H) {
    const int tid = threadIdx.x;
    const int lane = tid & 31;
    const int w2 = (tid >> 5) & 1;                      // which half of the row
    const int gw = blockIdx.x * 4 + (tid >> 6);         // (b,n)
    const int n = gw & (NN - 1);
    const int b = gw >> 12;

    const float4* __restrict__ Hrow = (const float4*)(H + (size_t)gw * EE);
    unsigned* __restrict__ ebm = g_ebm + (size_t)b * EE * EBW + (n >> 5);
    const unsigned bitv = 1u << (n & 31);
    const int cbase = w2 * 8;

    // prefetch the whole half-row: 8 independent LDG.128 in flight
    float4 hreg[8];
#pragma unroll
    for (int lc = 0; lc < 8; lc++)
        hreg[lc] = Hrow[(cbase + lc) * 32 + lane];

    unsigned nw0 = 0, nw1 = 0;
#pragma unroll
    for (int lc = 0; lc < 8; lc++) {
        const float4 h = hreg[lc];
        const int e0 = (cbase + lc) * 128 + lane * 4;
        const int c0 = h.x != 0.f, c1 = h.y != 0.f, c2 = h.z != 0.f, c3 = h.w != 0.f;

        if (c0) atomicOr(&ebm[(size_t)(e0 + 0) * EBW], bitv);
        if (c1) atomicOr(&ebm[(size_t)(e0 + 1) * EBW], bitv);
        if (c2) atomicOr(&ebm[(size_t)(e0 + 2) * EBW], bitv);
        if (c3) atomicOr(&ebm[(size_t)(e0 + 3) * EBW], bitv);

        const unsigned b0 = __ballot_sync(0xffffffffu, c0);
        const unsigned b1 = __ballot_sync(0xffffffffu, c1);
        const unsigned b2 = __ballot_sync(0xffffffffu, c2);
        const unsigned b3 = __ballot_sync(0xffffffffu, c3);
        if (lane == 2 * lc)          { nw0 = b0; nw1 = b1; }
        else if (lane == 2 * lc + 1) { nw0 = b2; nw1 = b3; }
    }
    if (lane < 16)
        ((uint2*)(g_nbm + (size_t)gw * NBW + w2 * 32))[lane] = make_uint2(nw0, nw1);
}

// ---------------- K3/K4: aggregation, fp16 rows (128B = 1 line = 1 wavefront) ------
// Warp per output row; decode bitmap -> smem u16 list; half-warp per gathered row
// (16 lanes x uint2); HADD2 pair-accumulate then convert once per 2 rows; packed
// fp32 accumulation.
template <int WPL, int CAP, bool HASBIAS, bool NATURAL, int M, int SRCROWS, bool OUTHALF>
__global__ __launch_bounds__(256)
void agg_kernel(const unsigned* __restrict__ bm, const __half* __restrict__ src,
                void* __restrict__ dstv, const float* __restrict__ bias) {
    __shared__ u16 sidx[8][CAP];

    const int tid = threadIdx.x;
    const int lane = tid & 31;
    const int wid = tid >> 5;
    const int gw = blockIdx.x * 8 + wid;   // (b,m)
    const int b = gw / M;

    // ---- decode bitmap -> smem index list ----
    unsigned w[WPL];
    const unsigned* __restrict__ W = bm + (size_t)gw * (WPL * 32);
    if (WPL == 4) {
        const uint4 v = ((const uint4*)W)[lane];
        w[0] = v.x; w[1] = v.y; w[2] = v.z; w[3] = v.w;
    } else {
        const uint2 v = ((const uint2*)W)[lane];
        w[0] = v.x; w[1] = v.y;
    }
    int cnt = 0;
#pragma unroll
    for (int k = 0; k < WPL; k++) cnt += __popc(w[k]);

    int pre = cnt;
#pragma unroll
    for (int d = 1; d < 32; d <<= 1) {
        int v = __shfl_up_sync(0xffffffffu, pre, d);
        if (lane >= d) pre += v;
    }
    const int deg = __shfl_sync(0xffffffffu, pre, 31);
    int off = pre - cnt;

    u16* __restrict__ s = sidx[wid];
#pragma unroll
    for (int k = 0; k < WPL; k++) {
        const int wi = lane * WPL + k;
        unsigned bits = w[k];
        while (bits) {
            const int t = __ffs(bits) - 1;
            bits &= bits - 1;
            const int idx = NATURAL ? (wi * 32 + t)
                                    : (((wi >> 2) << 7) + (wi & 3) + (t << 2));
            if (off < CAP) s[off] = (u16)idx;
            off++;
        }
    }
    __syncwarp();

    // ---- gather: half-warp per row; 8 rows (4 fp16 pairs) per iteration ----
    const int half = lane >> 4;
    const int hl = lane & 15;             // uint2 (4 halves = cols hl*4..hl*4+3)
    const uint2* __restrict__ S = (const uint2*)src + (size_t)b * (SRCROWS * 16);

    ull accA = 0ull, accB = 0ull;         // fp32 cols hl*4+{0,1} / {2,3}
    int i = 0;
    for (; i + 8 <= deg; i += 8) {
        const int r0 = (int)s[i + half];
        const int r1 = (int)s[i + 2 + half];
        const int r2 = (int)s[i + 4 + half];
        const int r3 = (int)s[i + 6 + half];
        const uint2 u0 = S[r0 * 16 + hl];
        const uint2 u1 = S[r1 * 16 + hl];
        const uint2 u2 = S[r2 * 16 + hl];
        const uint2 u3 = S[r3 * 16 + hl];
        const __half2 pa = __hadd2(*(const __half2*)&u0.x, *(const __half2*)&u1.x);
        const __half2 pb = __hadd2(*(const __half2*)&u0.y, *(const __half2*)&u1.y);
        const __half2 pc = __hadd2(*(const __half2*)&u2.x, *(const __half2*)&u3.x);
        const __half2 pd = __hadd2(*(const __half2*)&u2.y, *(const __half2*)&u3.y);
        accA = fadd2(accA, f2ull(__half22float2(pa)));
        accB = fadd2(accB, f2ull(__half22float2(pb)));
        accA = fadd2(accA, f2ull(__half22float2(pc)));
        accB = fadd2(accB, f2ull(__half22float2(pd)));
    }
    for (; i + 4 <= deg; i += 4) {
        const int r0 = (int)s[i + half];
        const int r1 = (int)s[i + 2 + half];
        const uint2 u0 = S[r0 * 16 + hl];
        const uint2 u1 = S[r1 * 16 + hl];
        const __half2 pa = __hadd2(*(const __half2*)&u0.x, *(const __half2*)&u1.x);
        const __half2 pb = __hadd2(*(const __half2*)&u0.y, *(const __half2*)&u1.y);
        accA = fadd2(accA, f2ull(__half22float2(pa)));
        accB = fadd2(accB, f2ull(__half22float2(pb)));
    }
    if (i + 2 <= deg) {
        const int r = (int)s[i + half];
        const uint2 u = S[r * 16 + hl];
        accA = fadd2(accA, f2ull(__half22float2(*(const __half2*)&u.x)));
        accB = fadd2(accB, f2ull(__half22float2(*(const __half2*)&u.y)));
        i += 2;
    }
    if (i < deg && half == 0) {
        const int r = (int)s[i];
        const uint2 u = S[r * 16 + hl];
        accA = fadd2(accA, f2ull(__half22float2(*(const __half2*)&u.x)));
        accB = fadd2(accB, f2ull(__half22float2(*(const __half2*)&u.y)));
    }

    // combine halves
    float v0 = ((const float2*)&accA)->x;
    float v1 = ((const float2*)&accA)->y;
    float v2 = ((const float2*)&accB)->x;
    float v3 = ((const float2*)&accB)->y;
    v0 += __shfl_xor_sync(0xffffffffu, v0, 16);
    v1 += __shfl_xor_sync(0xffffffffu, v1, 16);
    v2 += __shfl_xor_sync(0xffffffffu, v2, 16);
    v3 += __shfl_xor_sync(0xffffffffu, v3, 16);

    const float inv = 1.0f / (float)deg;   // degrees guaranteed > 0
    v0 *= inv; v1 *= inv; v2 *= inv; v3 *= inv;
    if (HASBIAS) {
        const float4 bv = ((const float4*)bias)[hl];
        v0 += bv.x; v1 += bv.y; v2 += bv.z; v3 += bv.w;
    }
    if (half == 0) {
        if (OUTHALF) {
            __half2 h0 = __float22half2_rn(make_float2(v0, v1));
            __half2 h1 = __float22half2_rn(make_float2(v2, v3));
            uint2 o;
            o.x = *(unsigned*)&h0;
            o.y = *(unsigned*)&h1;
            ((uint2*)((__half*)dstv + (size_t)gw * CC))[hl] = o;
        } else {
            ((float4*)((float*)dstv + (size_t)gw * CC))[hl] =
                make_float4(v0, v1, v2, v3);
        }
    }
}

// ---------------- launch ----------------
extern "C" void kernel_launch(void* const* d_in, const int* in_sizes, int n_in,
                              void* d_out, int out_size) {
    const float* x = (const float*)d_in[0];
    const float* H = (const float*)d_in[1];
    const float* theta = (const float*)d_in[2];
    const float* bias = (const float*)d_in[3];
    float* out = (float*)d_out;

    __half *xt, *he;
    unsigned *ebm, *nbm;
    cudaGetSymbolAddress((void**)&xt, g_xt);
    cudaGetSymbolAddress((void**)&he, g_he);
    cudaGetSymbolAddress((void**)&ebm, g_ebm);
    cudaGetSymbolAddress((void**)&nbm, g_nbm);

    // K0: zero edge bitmaps (4 MB)
    zero_kernel<<<1024, 256>>>();
    // K1: node transform -> fp16 xt
    xt_kernel<<<(BB * NN) / 8, 256>>>(x, theta);
    // K2: 2 warps per node row, prefetched -> node bitmaps + edge bitmaps
    build_kernel<<<(BB * NN) / 4, 256>>>(H);
    // K3: he = mean_{n in e} xt[n]  (fp16 out)
    agg_kernel<4, ECAP, false, true, EE, NN, true>
        <<<(BB * EE) / 8, 256>>>(ebm, xt, he, nullptr);
    // K4: out = mean_{e in n} he[e] + bias  (fp32 out)
    agg_kernel<2, NCAP, true, false, NN, EE, false>
        <<<(BB * NN) / 8, 256>>>(nbm, he, out, bias);
}